// round 14
// baseline (speedup 1.0000x reference)
#include <cuda_runtime.h>
#include <cuda_fp16.h>
#include <math_constants.h>
#include <cstdint>

// ---------------------------------------------------------------------------
// MultiHeadAttention: x[2,2048,2048] fp32, 4x W[2048,2048]
// Round 14: log2-domain softmax (ex2.approx.f16x2), rowsum via ones-MMA,
//           round_x merged into prep launch. GEMM unchanged (at HMMA wall).
// ---------------------------------------------------------------------------

#define BATCH   2
#define SEQ     2048
#define HID     2048
#define NH      16
#define HD      128
#define MTOT    (BATCH * SEQ)          // 4096

// scratch (fp16 operands)
__device__ __half g_X[MTOT * HID];
__device__ __half g_Q[MTOT * HID];
__device__ __half g_K[MTOT * HID];
__device__ __half g_V[MTOT * HID];
__device__ __half g_A[MTOT * HID];
__device__ __half g_WT[4ull * HID * HID];   // transposed weights [N,K]

// ---------------------------------------------------------------------------
__device__ __forceinline__ void mma_f16(float* d, const uint32_t* a, const uint32_t* b) {
    asm volatile(
        "mma.sync.aligned.m16n8k16.row.col.f32.f16.f16.f32 "
        "{%0,%1,%2,%3}, {%4,%5,%6,%7}, {%8,%9}, {%0,%1,%2,%3};"
        : "+f"(d[0]), "+f"(d[1]), "+f"(d[2]), "+f"(d[3])
        : "r"(a[0]), "r"(a[1]), "r"(a[2]), "r"(a[3]), "r"(b[0]), "r"(b[1]));
}

__device__ __forceinline__ void ldsm4(uint32_t* r, uint32_t a) {
    asm volatile("ldmatrix.sync.aligned.m8n8.x4.shared.b16 {%0,%1,%2,%3}, [%4];"
                 : "=r"(r[0]), "=r"(r[1]), "=r"(r[2]), "=r"(r[3]) : "r"(a));
}
__device__ __forceinline__ void ldsm4t(uint32_t* r, uint32_t a) {
    asm volatile("ldmatrix.sync.aligned.m8n8.x4.trans.shared.b16 {%0,%1,%2,%3}, [%4];"
                 : "=r"(r[0]), "=r"(r[1]), "=r"(r[2]), "=r"(r[3]) : "r"(a));
}

__device__ __forceinline__ uint32_t h2u(__half2 h) {
    return *reinterpret_cast<uint32_t*>(&h);
}

__device__ __forceinline__ uint32_t ex2_f16x2(uint32_t x) {
    uint32_t r;
    asm("ex2.approx.f16x2 %0, %1;" : "=r"(r) : "r"(x));
    return r;
}
__device__ __forceinline__ float ex2_f32(float x) {
    float r;
    asm("ex2.approx.f32 %0, %1;" : "=f"(r) : "f"(x));
    return r;
}

__device__ __forceinline__ void cp16(uint32_t dst, const void* src) {
    asm volatile("cp.async.cg.shared.global [%0], [%1], 16;" :: "r"(dst), "l"(src));
}

// ---------------------------------------------------------------------------
// Prep: z<4 -> weight transpose Wt[n,k] = half(W[k,n] * scale)
//       z==4 -> x fp32 -> fp16 copy (two 64x64 tiles per CTA)
// ---------------------------------------------------------------------------
__global__ __launch_bounds__(256)
void prep_all(const float* __restrict__ Wq, const float* __restrict__ Wk,
              const float* __restrict__ Wv, const float* __restrict__ Wo,
              __half* __restrict__ WT,
              const float* __restrict__ x, __half* __restrict__ X,
              float qscale)
{
    __shared__ float s[64][65];
    const int z = blockIdx.z;
    const int t = threadIdx.x;

    if (z == 4) {
        const int bx = blockIdx.x * 64;
        const int by = blockIdx.y * 64;
#pragma unroll
        for (int hrow = 0; hrow < 2; hrow++) {
            const int rb = hrow * 2048 + by;
#pragma unroll
            for (int p = 0; p < 4; p++) {
                const int row = p * 16 + (t >> 4);
                const int c   = (t & 15) * 4;
                float4 v = *(const float4*)&x[(size_t)(rb + row) * HID + bx + c];
                uint2 u = make_uint2(h2u(__floats2half2_rn(v.x, v.y)),
                                     h2u(__floats2half2_rn(v.z, v.w)));
                *(uint2*)&X[(size_t)(rb + row) * HID + bx + c] = u;
            }
        }
        return;
    }

    const float* W = (z == 0) ? Wq : (z == 1) ? Wk : (z == 2) ? Wv : Wo;
    const float scale = (z == 0) ? qscale : 1.0f;
    __half* Wt = WT + (size_t)z * HID * HID;

    const int bn = blockIdx.x * 64;
    const int bk = blockIdx.y * 64;

#pragma unroll
    for (int p = 0; p < 4; p++) {
        const int kl = p * 16 + (t >> 4);
        const int nl = (t & 15) * 4;
        float4 v = *(const float4*)&W[(size_t)(bk + kl) * HID + bn + nl];
        s[kl][nl + 0] = v.x; s[kl][nl + 1] = v.y;
        s[kl][nl + 2] = v.z; s[kl][nl + 3] = v.w;
    }
    __syncthreads();

#pragma unroll
    for (int p = 0; p < 4; p++) {
        const int nl = p * 16 + (t >> 4);
        const int kg = (t & 15) * 4;
        __half h0 = __float2half_rn(s[kg + 0][nl] * scale);
        __half h1 = __float2half_rn(s[kg + 1][nl] * scale);
        __half h2 = __float2half_rn(s[kg + 2][nl] * scale);
        __half h3 = __float2half_rn(s[kg + 3][nl] * scale);
        uint2 u = make_uint2(h2u(__halves2half2(h0, h1)),
                             h2u(__halves2half2(h2, h3)));
        *(uint2*)&Wt[(size_t)(bn + nl) * HID + bk + kg] = u;
    }
}

// ---------------------------------------------------------------------------
// fp16 mma GEMM (unchanged: 128 thr, 4 warps of 64x64, 2-stage cp.async).
// ---------------------------------------------------------------------------
#define TBM 128
#define TBN 128
#define TBK 32
#define KCH (HID / TBK)                 // 64
#define SR2 20
#define STG (TBM * SR2)

__global__ __launch_bounds__(128, 2)
void gemm_f16(const __half* __restrict__ A, const __half* __restrict__ BtBase,
              void* C0, void* C1, void* C2, int permute)
{
    __shared__ uint32_t dsm[4 * STG];   // 40KB

    const __half* Bt = BtBase + (size_t)blockIdx.z * HID * HID;
    void* Cp = (blockIdx.z == 0) ? C0 : (blockIdx.z == 1 ? C1 : C2);

    const int t    = threadIdx.x;
    const int wid  = t >> 5;
    const int lane = t & 31;
    const int grp  = lane >> 2;
    const int tid4 = lane & 3;
    const int m0   = blockIdx.y * TBM;
    const int n0   = blockIdx.x * TBN;
    const int wm   = (wid & 1) * 64;
    const int wn   = (wid >> 1) * 64;

    const uint32_t sbase = (uint32_t)__cvta_generic_to_shared(dsm);

    const int lr  = t >> 2;
    const int c16 = t & 3;
    const __half* Ab = A  + (size_t)(m0 + lr) * HID + c16 * 8;
    const __half* Bb = Bt + (size_t)(n0 + lr) * HID + c16 * 8;

    float acc[4][8][4];
#pragma unroll
    for (int mt = 0; mt < 4; mt++)
#pragma unroll
        for (int nt = 0; nt < 8; nt++)
#pragma unroll
            for (int r = 0; r < 4; r++) acc[mt][nt][r] = 0.f;

#define LOAD_STAGE(st, kk) do {                                               \
    const uint32_t dA = sbase + ((st) * STG + lr * SR2 + c16 * 4) * 4;        \
    const uint32_t dB = dA + 2 * STG * 4;                                     \
    _Pragma("unroll")                                                         \
    for (int p = 0; p < 4; p++) {                                             \
        cp16(dA + p * 32 * SR2 * 4, Ab + (size_t)p * 32 * HID + (kk));        \
        cp16(dB + p * 32 * SR2 * 4, Bb + (size_t)p * 32 * HID + (kk));        \
    }                                                                         \
    asm volatile("cp.async.commit_group;");                                   \
} while (0)

    LOAD_STAGE(0, 0);

    for (int c = 0; c < KCH; ++c) {
        if (c + 1 < KCH) {
            LOAD_STAGE((c + 1) & 1, (c + 1) * TBK);
            asm volatile("cp.async.wait_group 1;");
        } else {
            asm volatile("cp.async.wait_group 0;");
        }
        __syncthreads();

        const uint32_t* cA = dsm + (c & 1) * STG;
        const uint32_t* cB = cA + 2 * STG;

#pragma unroll
        for (int ks = 0; ks < 2; ks++) {
            const int k2 = ks * 8;
            uint32_t af[4][4], bf[8][2];
#pragma unroll
            for (int mt = 0; mt < 4; mt++) {
                const int r = wm + mt * 16 + grp;
                af[mt][0] = cA[r * SR2 + k2 + tid4];
                af[mt][1] = cA[(r + 8) * SR2 + k2 + tid4];
                af[mt][2] = cA[r * SR2 + k2 + tid4 + 4];
                af[mt][3] = cA[(r + 8) * SR2 + k2 + tid4 + 4];
            }
#pragma unroll
            for (int nt = 0; nt < 8; nt++) {
                const int n = wn + nt * 8 + grp;
                bf[nt][0] = cB[n * SR2 + k2 + tid4];
                bf[nt][1] = cB[n * SR2 + k2 + tid4 + 4];
            }
#pragma unroll
            for (int mt = 0; mt < 4; mt++)
#pragma unroll
                for (int nt = 0; nt < 8; nt++)
                    mma_f16(acc[mt][nt], af[mt], bf[nt]);
        }
        __syncthreads();
    }

#pragma unroll
    for (int mt = 0; mt < 4; mt++) {
#pragma unroll
        for (int nt = 0; nt < 8; nt++) {
            const int row0 = m0 + wm + mt * 16 + grp;
            const int col  = n0 + wn + nt * 8 + tid4 * 2;
#pragma unroll
            for (int h = 0; h < 2; h++) {
                const int row = row0 + h * 8;
                if (permute) {
                    const int b = row >> 11, s = row & 2047;
                    const int hh = col >> 7, dc = col & 127;
                    __half* Ch = (__half*)Cp;
                    *(__half2*)&Ch[((size_t)((b * NH + hh) * SEQ + s)) * HD + dc] =
                        __floats2half2_rn(acc[mt][nt][h * 2], acc[mt][nt][h * 2 + 1]);
                } else {
                    float* Cf = (float*)Cp;
                    *(float2*)&Cf[(size_t)row * HID + col] =
                        make_float2(acc[mt][nt][h * 2], acc[mt][nt][h * 2 + 1]);
                }
            }
        }
    }
}

// ---------------------------------------------------------------------------
// fp16 flash attention, log2-domain softmax edition.
// Q pre-scaled by (1/sqrt(hd))*log2e via Wq; S is in exp2 domain.
// P via ex2.approx.f16x2 into register A-fragments; rowsum l via ones-MMA.
// ---------------------------------------------------------------------------
#define QW 68                            // words per row (64 data + 4 pad)

__global__ __launch_bounds__(128)
void attn_f16_kernel(const __half* __restrict__ Q, const __half* __restrict__ K,
                     const __half* __restrict__ V, __half* __restrict__ O)
{
    extern __shared__ uint32_t dsm2[];
    uint32_t* sQ = dsm2;                 // 64*QW
    uint32_t* sK = dsm2 + 64 * QW;
    uint32_t* sV = dsm2 + 2 * 64 * QW;

    const int t    = threadIdx.x;
    const int w    = t >> 5;
    const int lane = t & 31;
    const int grp  = lane >> 2;
    const int tid4 = lane & 3;
    const int qb   = gridDim.x - 1 - blockIdx.x;   // heavy CTAs first
    const int bh   = blockIdx.y;

    const uint32_t sQ_u = (uint32_t)__cvta_generic_to_shared(sQ);
    const uint32_t sK_u = (uint32_t)__cvta_generic_to_shared(sK);
    const uint32_t sV_u = (uint32_t)__cvta_generic_to_shared(sV);

    const int rsel  = (lane & 7) + ((lane >> 3) & 1) * 8;
    const int csel2 = (lane >> 4) & 1;
    const int rselK = (lane & 7) + ((lane >> 4) & 1) * 8;
    const int cselK = (lane >> 3) & 1;

    const uint32_t aBase = sQ_u + (uint32_t)(((w * 16 + rsel) * QW + csel2 * 4) * 4);
    const uint32_t kBase = sK_u + (uint32_t)((rselK * QW + cselK * 4) * 4);
    const uint32_t vBase = sV_u + (uint32_t)((rsel * QW + csel2 * 4) * 4);

    const __half* Qb = Q + ((size_t)bh * SEQ + qb * 64) * HD;
    const __half* Kb = K + (size_t)bh * SEQ * HD;
    const __half* Vb = V + (size_t)bh * SEQ * HD;

#pragma unroll
    for (int p = 0; p < 8; p++) {
        const int row = p * 8 + (t >> 4);
        const int c16 = t & 15;
        *(uint4*)&sQ[row * QW + c16 * 4] =
            *(const uint4*)&Qb[(size_t)row * HD + c16 * 8];
    }

    const int r0 = w * 16 + grp;
    float m0 = -CUDART_INF_F, m1 = -CUDART_INF_F;
    float ol[4] = {0.f, 0.f, 0.f, 0.f};           // rowsum accumulator (ones-MMA)
    float o[16][4];
#pragma unroll
    for (int nt = 0; nt < 16; nt++)
#pragma unroll
        for (int r = 0; r < 4; r++) o[nt][r] = 0.f;

    const uint32_t ONES2 = 0x3C003C00u;           // half2(1.0, 1.0)
    uint32_t bones[2] = {ONES2, ONES2};

    for (int kb = 0; kb <= qb; kb++) {
#pragma unroll
        for (int p = 0; p < 8; p++) {
            const int row = p * 8 + (t >> 4);
            const int c16 = t & 15;
            *(uint4*)&sK[row * QW + c16 * 4] =
                *(const uint4*)&Kb[(size_t)(kb * 64 + row) * HD + c16 * 8];
            *(uint4*)&sV[row * QW + c16 * 4] =
                *(const uint4*)&Vb[(size_t)(kb * 64 + row) * HD + c16 * 8];
        }
        __syncthreads();

        float s[8][4];
#pragma unroll
        for (int nt = 0; nt < 8; nt++)
#pragma unroll
            for (int r = 0; r < 4; r++) s[nt][r] = 0.f;

#pragma unroll
        for (int ks = 0; ks < 8; ks++) {
            uint32_t a[4];
            ldsm4(a, aBase + ks * 32);
#pragma unroll
            for (int ntp = 0; ntp < 4; ntp++) {
                uint32_t b[4];
                ldsm4(b, kBase + (uint32_t)(ntp * 16 * QW * 4) + ks * 32);
                mma_f16(s[2 * ntp],     a, b);
                mma_f16(s[2 * ntp + 1], a, b + 2);
            }
        }

        if (kb == qb) {
            const int rg0 = qb * 64 + r0;
            const int rg1 = rg0 + 8;
#pragma unroll
            for (int nt = 0; nt < 8; nt++) {
                const int c0 = kb * 64 + nt * 8 + 2 * tid4;
                if (c0     > rg0) s[nt][0] = -CUDART_INF_F;
                if (c0 + 1 > rg0) s[nt][1] = -CUDART_INF_F;
                if (c0     > rg1) s[nt][2] = -CUDART_INF_F;
                if (c0 + 1 > rg1) s[nt][3] = -CUDART_INF_F;
            }
        }

        // ---- online softmax, log2 domain ----
        float rm0 = -CUDART_INF_F, rm1 = -CUDART_INF_F;
#pragma unroll
        for (int nt = 0; nt < 8; nt++) {
            rm0 = fmaxf(rm0, fmaxf(s[nt][0], s[nt][1]));
            rm1 = fmaxf(rm1, fmaxf(s[nt][2], s[nt][3]));
        }
        rm0 = fmaxf(rm0, __shfl_xor_sync(0xffffffffu, rm0, 1));
        rm0 = fmaxf(rm0, __shfl_xor_sync(0xffffffffu, rm0, 2));
        rm1 = fmaxf(rm1, __shfl_xor_sync(0xffffffffu, rm1, 1));
        rm1 = fmaxf(rm1, __shfl_xor_sync(0xffffffffu, rm1, 2));

        const float mn0 = fmaxf(m0, rm0);
        const float mn1 = fmaxf(m1, rm1);
        const float cf0 = ex2_f32(m0 - mn0);
        const float cf1 = ex2_f32(m1 - mn1);
        m0 = mn0; m1 = mn1;

        uint32_t pa[4][4];                 // P as A-fragments per kt
#pragma unroll
        for (int nt = 0; nt < 8; nt++) {
            uint32_t x0 = h2u(__floats2half2_rn(s[nt][0] - m0, s[nt][1] - m0));
            uint32_t x1 = h2u(__floats2half2_rn(s[nt][2] - m1, s[nt][3] - m1));
            const int kt = nt >> 1, hi = (nt & 1) * 2;
            pa[kt][hi]     = ex2_f16x2(x0);
            pa[kt][hi + 1] = ex2_f16x2(x1);
        }

        ol[0] *= cf0; ol[1] *= cf0; ol[2] *= cf1; ol[3] *= cf1;
#pragma unroll
        for (int nt = 0; nt < 16; nt++) {
            o[nt][0] *= cf0; o[nt][1] *= cf0;
            o[nt][2] *= cf1; o[nt][3] *= cf1;
        }

        // ---- O += P V (and l += P 1) ----
#pragma unroll
        for (int kt = 0; kt < 4; kt++) {
            mma_f16(ol, pa[kt], bones);
            const uint32_t vk = vBase + (uint32_t)(kt * 16 * QW * 4);
#pragma unroll
            for (int dtp = 0; dtp < 8; dtp++) {
                uint32_t b[4];
                ldsm4t(b, vk + dtp * 32);
                mma_f16(o[2 * dtp],     pa[kt], b);
                mma_f16(o[2 * dtp + 1], pa[kt], b + 2);
            }
        }
        __syncthreads();
    }

    // ---- epilogue ----
    const int bb = bh >> 4, hh = bh & 15;
    const float i0 = 1.f / ol[0];
    const float i1 = 1.f / ol[2];
    const int sg = qb * 64 + r0;
#pragma unroll
    for (int nt = 0; nt < 16; nt++) {
        const int col = hh * 128 + nt * 8 + 2 * tid4;
        *(__half2*)&O[((size_t)(bb * SEQ + sg)) * HID + col] =
            __floats2half2_rn(o[nt][0] * i0, o[nt][1] * i0);
        *(__half2*)&O[((size_t)(bb * SEQ + sg + 8)) * HID + col] =
            __floats2half2_rn(o[nt][2] * i1, o[nt][3] * i1);
    }
}

#define ATTN_SMEM_BYTES (3 * 64 * QW * 4)   // 52224

// ---------------------------------------------------------------------------
extern "C" void kernel_launch(void* const* d_in, const int* in_sizes, int n_in,
                              void* d_out, int out_size)
{
    const float* x  = (const float*)d_in[0];
    const float* Wq = (const float*)d_in[1];
    const float* Wk = (const float*)d_in[2];
    const float* Wv = (const float*)d_in[3];
    const float* Wo = (const float*)d_in[4];

    __half *Xp, *Qp, *Kp, *Vp, *Ap, *WTp;
    cudaGetSymbolAddress((void**)&Xp,  g_X);
    cudaGetSymbolAddress((void**)&Qp,  g_Q);
    cudaGetSymbolAddress((void**)&Kp,  g_K);
    cudaGetSymbolAddress((void**)&Vp,  g_V);
    cudaGetSymbolAddress((void**)&Ap,  g_A);
    cudaGetSymbolAddress((void**)&WTp, g_WT);

    cudaFuncSetAttribute(attn_f16_kernel,
                         cudaFuncAttributeMaxDynamicSharedMemorySize,
                         ATTN_SMEM_BYTES);

    const size_t WSZ = (size_t)HID * HID;
    // (1/sqrt(128)) * log2(e): Q scale folded into Wq -> S in exp2 domain
    const float qscale = 0.08838834764831845f * 1.4426950408889634f;

    prep_all<<<dim3(HID / 64, HID / 64, 5), 256>>>(Wq, Wk, Wv, Wo, WTp, x, Xp, qscale);

    gemm_f16<<<dim3(HID / TBN, MTOT / TBM, 3), 128>>>(Xp, WTp, Qp, Kp, Vp, 1);

    attn_f16_kernel<<<dim3(SEQ / 64, BATCH * NH), 128, ATTN_SMEM_BYTES>>>(Qp, Kp, Vp, Ap);

    gemm_f16<<<dim3(HID / TBN, MTOT / TBM, 1), 128>>>(Ap, WTp + 3 * WSZ,
                                                      d_out, nullptr, nullptr, 0);
}

// round 17
// speedup vs baseline: 1.5160x; 1.5160x over previous
#include <cuda_runtime.h>
#include <cuda_fp16.h>
#include <math_constants.h>
#include <cstdint>

// ---------------------------------------------------------------------------
// MultiHeadAttention: x[2,2048,2048] fp32, 4x W[2048,2048]
// Round 15: controlled revert to round-13 attention (expf softmax, shuffle
//           rowsum). Only retained change: prep merged into one launch
//           (weight transposes z=0..3, x->fp16 z=4). GEMM unchanged.
// ---------------------------------------------------------------------------

#define BATCH   2
#define SEQ     2048
#define HID     2048
#define NH      16
#define HD      128
#define MTOT    (BATCH * SEQ)          // 4096

// scratch (fp16 operands)
__device__ __half g_X[MTOT * HID];
__device__ __half g_Q[MTOT * HID];
__device__ __half g_K[MTOT * HID];
__device__ __half g_V[MTOT * HID];
__device__ __half g_A[MTOT * HID];
__device__ __half g_WT[4ull * HID * HID];   // transposed weights [N,K]

// ---------------------------------------------------------------------------
__device__ __forceinline__ void mma_f16(float* d, const uint32_t* a, const uint32_t* b) {
    asm volatile(
        "mma.sync.aligned.m16n8k16.row.col.f32.f16.f16.f32 "
        "{%0,%1,%2,%3}, {%4,%5,%6,%7}, {%8,%9}, {%0,%1,%2,%3};"
        : "+f"(d[0]), "+f"(d[1]), "+f"(d[2]), "+f"(d[3])
        : "r"(a[0]), "r"(a[1]), "r"(a[2]), "r"(a[3]), "r"(b[0]), "r"(b[1]));
}

__device__ __forceinline__ void ldsm4(uint32_t* r, uint32_t a) {
    asm volatile("ldmatrix.sync.aligned.m8n8.x4.shared.b16 {%0,%1,%2,%3}, [%4];"
                 : "=r"(r[0]), "=r"(r[1]), "=r"(r[2]), "=r"(r[3]) : "r"(a));
}
__device__ __forceinline__ void ldsm4t(uint32_t* r, uint32_t a) {
    asm volatile("ldmatrix.sync.aligned.m8n8.x4.trans.shared.b16 {%0,%1,%2,%3}, [%4];"
                 : "=r"(r[0]), "=r"(r[1]), "=r"(r[2]), "=r"(r[3]) : "r"(a));
}

__device__ __forceinline__ uint32_t h2u(__half2 h) {
    return *reinterpret_cast<uint32_t*>(&h);
}

__device__ __forceinline__ void cp16(uint32_t dst, const void* src) {
    asm volatile("cp.async.cg.shared.global [%0], [%1], 16;" :: "r"(dst), "l"(src));
}

// ---------------------------------------------------------------------------
// Prep: z<4 -> weight transpose Wt[n,k] = half(W[k,n] * scale)
//       z==4 -> x fp32 -> fp16 copy
// ---------------------------------------------------------------------------
__global__ __launch_bounds__(256)
void prep_all(const float* __restrict__ Wq, const float* __restrict__ Wk,
              const float* __restrict__ Wv, const float* __restrict__ Wo,
              __half* __restrict__ WT,
              const float* __restrict__ x, __half* __restrict__ X,
              float qscale)
{
    __shared__ float s[64][65];
    const int z = blockIdx.z;
    const int t = threadIdx.x;

    if (z == 4) {
        const int bx = blockIdx.x * 64;
        const int by = blockIdx.y * 64;
#pragma unroll
        for (int hrow = 0; hrow < 2; hrow++) {
            const int rb = hrow * 2048 + by;
#pragma unroll
            for (int p = 0; p < 4; p++) {
                const int row = p * 16 + (t >> 4);
                const int c   = (t & 15) * 4;
                float4 v = *(const float4*)&x[(size_t)(rb + row) * HID + bx + c];
                uint2 u = make_uint2(h2u(__floats2half2_rn(v.x, v.y)),
                                     h2u(__floats2half2_rn(v.z, v.w)));
                *(uint2*)&X[(size_t)(rb + row) * HID + bx + c] = u;
            }
        }
        return;
    }

    const float* W = (z == 0) ? Wq : (z == 1) ? Wk : (z == 2) ? Wv : Wo;
    const float scale = (z == 0) ? qscale : 1.0f;
    __half* Wt = WT + (size_t)z * HID * HID;

    const int bn = blockIdx.x * 64;
    const int bk = blockIdx.y * 64;

#pragma unroll
    for (int p = 0; p < 4; p++) {
        const int kl = p * 16 + (t >> 4);
        const int nl = (t & 15) * 4;
        float4 v = *(const float4*)&W[(size_t)(bk + kl) * HID + bn + nl];
        s[kl][nl + 0] = v.x; s[kl][nl + 1] = v.y;
        s[kl][nl + 2] = v.z; s[kl][nl + 3] = v.w;
    }
    __syncthreads();

#pragma unroll
    for (int p = 0; p < 4; p++) {
        const int nl = p * 16 + (t >> 4);
        const int kg = (t & 15) * 4;
        __half h0 = __float2half_rn(s[kg + 0][nl] * scale);
        __half h1 = __float2half_rn(s[kg + 1][nl] * scale);
        __half h2 = __float2half_rn(s[kg + 2][nl] * scale);
        __half h3 = __float2half_rn(s[kg + 3][nl] * scale);
        uint2 u = make_uint2(h2u(__halves2half2(h0, h1)),
                             h2u(__halves2half2(h2, h3)));
        *(uint2*)&Wt[(size_t)(bn + nl) * HID + bk + kg] = u;
    }
}

// ---------------------------------------------------------------------------
// fp16 mma GEMM (unchanged: 128 thr, 4 warps of 64x64, 2-stage cp.async).
// ---------------------------------------------------------------------------
#define TBM 128
#define TBN 128
#define TBK 32
#define KCH (HID / TBK)                 // 64
#define SR2 20
#define STG (TBM * SR2)

__global__ __launch_bounds__(128, 2)
void gemm_f16(const __half* __restrict__ A, const __half* __restrict__ BtBase,
              void* C0, void* C1, void* C2, int permute)
{
    __shared__ uint32_t dsm[4 * STG];   // 40KB

    const __half* Bt = BtBase + (size_t)blockIdx.z * HID * HID;
    void* Cp = (blockIdx.z == 0) ? C0 : (blockIdx.z == 1 ? C1 : C2);

    const int t    = threadIdx.x;
    const int wid  = t >> 5;
    const int lane = t & 31;
    const int grp  = lane >> 2;
    const int tid4 = lane & 3;
    const int m0   = blockIdx.y * TBM;
    const int n0   = blockIdx.x * TBN;
    const int wm   = (wid & 1) * 64;
    const int wn   = (wid >> 1) * 64;

    const uint32_t sbase = (uint32_t)__cvta_generic_to_shared(dsm);

    const int lr  = t >> 2;
    const int c16 = t & 3;
    const __half* Ab = A  + (size_t)(m0 + lr) * HID + c16 * 8;
    const __half* Bb = Bt + (size_t)(n0 + lr) * HID + c16 * 8;

    float acc[4][8][4];
#pragma unroll
    for (int mt = 0; mt < 4; mt++)
#pragma unroll
        for (int nt = 0; nt < 8; nt++)
#pragma unroll
            for (int r = 0; r < 4; r++) acc[mt][nt][r] = 0.f;

#define LOAD_STAGE(st, kk) do {                                               \
    const uint32_t dA = sbase + ((st) * STG + lr * SR2 + c16 * 4) * 4;        \
    const uint32_t dB = dA + 2 * STG * 4;                                     \
    _Pragma("unroll")                                                         \
    for (int p = 0; p < 4; p++) {                                             \
        cp16(dA + p * 32 * SR2 * 4, Ab + (size_t)p * 32 * HID + (kk));        \
        cp16(dB + p * 32 * SR2 * 4, Bb + (size_t)p * 32 * HID + (kk));        \
    }                                                                         \
    asm volatile("cp.async.commit_group;");                                   \
} while (0)

    LOAD_STAGE(0, 0);

    for (int c = 0; c < KCH; ++c) {
        if (c + 1 < KCH) {
            LOAD_STAGE((c + 1) & 1, (c + 1) * TBK);
            asm volatile("cp.async.wait_group 1;");
        } else {
            asm volatile("cp.async.wait_group 0;");
        }
        __syncthreads();

        const uint32_t* cA = dsm + (c & 1) * STG;
        const uint32_t* cB = cA + 2 * STG;

#pragma unroll
        for (int ks = 0; ks < 2; ks++) {
            const int k2 = ks * 8;
            uint32_t af[4][4], bf[8][2];
#pragma unroll
            for (int mt = 0; mt < 4; mt++) {
                const int r = wm + mt * 16 + grp;
                af[mt][0] = cA[r * SR2 + k2 + tid4];
                af[mt][1] = cA[(r + 8) * SR2 + k2 + tid4];
                af[mt][2] = cA[r * SR2 + k2 + tid4 + 4];
                af[mt][3] = cA[(r + 8) * SR2 + k2 + tid4 + 4];
            }
#pragma unroll
            for (int nt = 0; nt < 8; nt++) {
                const int n = wn + nt * 8 + grp;
                bf[nt][0] = cB[n * SR2 + k2 + tid4];
                bf[nt][1] = cB[n * SR2 + k2 + tid4 + 4];
            }
#pragma unroll
            for (int mt = 0; mt < 4; mt++)
#pragma unroll
                for (int nt = 0; nt < 8; nt++)
                    mma_f16(acc[mt][nt], af[mt], bf[nt]);
        }
        __syncthreads();
    }

#pragma unroll
    for (int mt = 0; mt < 4; mt++) {
#pragma unroll
        for (int nt = 0; nt < 8; nt++) {
            const int row0 = m0 + wm + mt * 16 + grp;
            const int col  = n0 + wn + nt * 8 + tid4 * 2;
#pragma unroll
            for (int h = 0; h < 2; h++) {
                const int row = row0 + h * 8;
                if (permute) {
                    const int b = row >> 11, s = row & 2047;
                    const int hh = col >> 7, dc = col & 127;
                    __half* Ch = (__half*)Cp;
                    *(__half2*)&Ch[((size_t)((b * NH + hh) * SEQ + s)) * HD + dc] =
                        __floats2half2_rn(acc[mt][nt][h * 2], acc[mt][nt][h * 2 + 1]);
                } else {
                    float* Cf = (float*)Cp;
                    *(float2*)&Cf[(size_t)row * HID + col] =
                        make_float2(acc[mt][nt][h * 2], acc[mt][nt][h * 2 + 1]);
                }
            }
        }
    }
}

// ---------------------------------------------------------------------------
// fp16 flash attention — exact round-13 version (expf softmax, shuffle rowsum,
// ldmatrix fragments, register-resident P).
// ---------------------------------------------------------------------------
#define QW 68                            // words per row (64 data + 4 pad)

__global__ __launch_bounds__(128)
void attn_f16_kernel(const __half* __restrict__ Q, const __half* __restrict__ K,
                     const __half* __restrict__ V, __half* __restrict__ O)
{
    extern __shared__ uint32_t dsm2[];
    uint32_t* sQ = dsm2;                 // 64*QW
    uint32_t* sK = dsm2 + 64 * QW;
    uint32_t* sV = dsm2 + 2 * 64 * QW;

    const int t    = threadIdx.x;
    const int w    = t >> 5;
    const int lane = t & 31;
    const int grp  = lane >> 2;
    const int tid4 = lane & 3;
    const int qb   = gridDim.x - 1 - blockIdx.x;   // heavy CTAs first
    const int bh   = blockIdx.y;

    const uint32_t sQ_u = (uint32_t)__cvta_generic_to_shared(sQ);
    const uint32_t sK_u = (uint32_t)__cvta_generic_to_shared(sK);
    const uint32_t sV_u = (uint32_t)__cvta_generic_to_shared(sV);

    const int rsel  = (lane & 7) + ((lane >> 3) & 1) * 8;
    const int csel2 = (lane >> 4) & 1;
    const int rselK = (lane & 7) + ((lane >> 4) & 1) * 8;
    const int cselK = (lane >> 3) & 1;

    const uint32_t aBase = sQ_u + (uint32_t)(((w * 16 + rsel) * QW + csel2 * 4) * 4);
    const uint32_t kBase = sK_u + (uint32_t)((rselK * QW + cselK * 4) * 4);
    const uint32_t vBase = sV_u + (uint32_t)((rsel * QW + csel2 * 4) * 4);

    const __half* Qb = Q + ((size_t)bh * SEQ + qb * 64) * HD;
    const __half* Kb = K + (size_t)bh * SEQ * HD;
    const __half* Vb = V + (size_t)bh * SEQ * HD;

#pragma unroll
    for (int p = 0; p < 8; p++) {
        const int row = p * 8 + (t >> 4);
        const int c16 = t & 15;
        *(uint4*)&sQ[row * QW + c16 * 4] =
            *(const uint4*)&Qb[(size_t)row * HD + c16 * 8];
    }

    const int r0 = w * 16 + grp;
    float m0 = -CUDART_INF_F, m1 = -CUDART_INF_F;
    float l0 = 0.f, l1 = 0.f;
    float o[16][4];
#pragma unroll
    for (int nt = 0; nt < 16; nt++)
#pragma unroll
        for (int r = 0; r < 4; r++) o[nt][r] = 0.f;

    for (int kb = 0; kb <= qb; kb++) {
#pragma unroll
        for (int p = 0; p < 8; p++) {
            const int row = p * 8 + (t >> 4);
            const int c16 = t & 15;
            *(uint4*)&sK[row * QW + c16 * 4] =
                *(const uint4*)&Kb[(size_t)(kb * 64 + row) * HD + c16 * 8];
            *(uint4*)&sV[row * QW + c16 * 4] =
                *(const uint4*)&Vb[(size_t)(kb * 64 + row) * HD + c16 * 8];
        }
        __syncthreads();

        float s[8][4];
#pragma unroll
        for (int nt = 0; nt < 8; nt++)
#pragma unroll
            for (int r = 0; r < 4; r++) s[nt][r] = 0.f;

#pragma unroll
        for (int ks = 0; ks < 8; ks++) {
            uint32_t a[4];
            ldsm4(a, aBase + ks * 32);
#pragma unroll
            for (int ntp = 0; ntp < 4; ntp++) {
                uint32_t b[4];
                ldsm4(b, kBase + (uint32_t)(ntp * 16 * QW * 4) + ks * 32);
                mma_f16(s[2 * ntp],     a, b);
                mma_f16(s[2 * ntp + 1], a, b + 2);
            }
        }

        if (kb == qb) {
            const int rg0 = qb * 64 + r0;
            const int rg1 = rg0 + 8;
#pragma unroll
            for (int nt = 0; nt < 8; nt++) {
                const int c0 = kb * 64 + nt * 8 + 2 * tid4;
                if (c0     > rg0) s[nt][0] = -CUDART_INF_F;
                if (c0 + 1 > rg0) s[nt][1] = -CUDART_INF_F;
                if (c0     > rg1) s[nt][2] = -CUDART_INF_F;
                if (c0 + 1 > rg1) s[nt][3] = -CUDART_INF_F;
            }
        }

        float rm0 = -CUDART_INF_F, rm1 = -CUDART_INF_F;
#pragma unroll
        for (int nt = 0; nt < 8; nt++) {
            rm0 = fmaxf(rm0, fmaxf(s[nt][0], s[nt][1]));
            rm1 = fmaxf(rm1, fmaxf(s[nt][2], s[nt][3]));
        }
        rm0 = fmaxf(rm0, __shfl_xor_sync(0xffffffffu, rm0, 1));
        rm0 = fmaxf(rm0, __shfl_xor_sync(0xffffffffu, rm0, 2));
        rm1 = fmaxf(rm1, __shfl_xor_sync(0xffffffffu, rm1, 1));
        rm1 = fmaxf(rm1, __shfl_xor_sync(0xffffffffu, rm1, 2));

        const float mn0 = fmaxf(m0, rm0);
        const float mn1 = fmaxf(m1, rm1);
        const float cf0 = __expf(m0 - mn0);
        const float cf1 = __expf(m1 - mn1);
        m0 = mn0; m1 = mn1;

        float ps0 = 0.f, ps1 = 0.f;
        uint32_t pa[4][4];                 // P as A-fragments per kt
#pragma unroll
        for (int nt = 0; nt < 8; nt++) {
            const float p00 = __expf(s[nt][0] - m0);
            const float p01 = __expf(s[nt][1] - m0);
            const float p10 = __expf(s[nt][2] - m1);
            const float p11 = __expf(s[nt][3] - m1);
            ps0 += p00 + p01;
            ps1 += p10 + p11;
            const int kt = nt >> 1, hi = (nt & 1) * 2;
            pa[kt][hi]     = h2u(__floats2half2_rn(p00, p01));
            pa[kt][hi + 1] = h2u(__floats2half2_rn(p10, p11));
        }
        ps0 += __shfl_xor_sync(0xffffffffu, ps0, 1);
        ps0 += __shfl_xor_sync(0xffffffffu, ps0, 2);
        ps1 += __shfl_xor_sync(0xffffffffu, ps1, 1);
        ps1 += __shfl_xor_sync(0xffffffffu, ps1, 2);
        l0 = l0 * cf0 + ps0;
        l1 = l1 * cf1 + ps1;

#pragma unroll
        for (int nt = 0; nt < 16; nt++) {
            o[nt][0] *= cf0; o[nt][1] *= cf0;
            o[nt][2] *= cf1; o[nt][3] *= cf1;
        }

#pragma unroll
        for (int kt = 0; kt < 4; kt++) {
            const uint32_t vk = vBase + (uint32_t)(kt * 16 * QW * 4);
#pragma unroll
            for (int dtp = 0; dtp < 8; dtp++) {
                uint32_t b[4];
                ldsm4t(b, vk + dtp * 32);
                mma_f16(o[2 * dtp],     pa[kt], b);
                mma_f16(o[2 * dtp + 1], pa[kt], b + 2);
            }
        }
        __syncthreads();
    }

    const int bb = bh >> 4, hh = bh & 15;
    const float i0 = 1.f / l0;
    const float i1 = 1.f / l1;
    const int sg = qb * 64 + r0;
#pragma unroll
    for (int nt = 0; nt < 16; nt++) {
        const int col = hh * 128 + nt * 8 + 2 * tid4;
        *(__half2*)&O[((size_t)(bb * SEQ + sg)) * HID + col] =
            __floats2half2_rn(o[nt][0] * i0, o[nt][1] * i0);
        *(__half2*)&O[((size_t)(bb * SEQ + sg + 8)) * HID + col] =
            __floats2half2_rn(o[nt][2] * i1, o[nt][3] * i1);
    }
}

#define ATTN_SMEM_BYTES (3 * 64 * QW * 4)   // 52224

// ---------------------------------------------------------------------------
extern "C" void kernel_launch(void* const* d_in, const int* in_sizes, int n_in,
                              void* d_out, int out_size)
{
    const float* x  = (const float*)d_in[0];
    const float* Wq = (const float*)d_in[1];
    const float* Wk = (const float*)d_in[2];
    const float* Wv = (const float*)d_in[3];
    const float* Wo = (const float*)d_in[4];

    __half *Xp, *Qp, *Kp, *Vp, *Ap, *WTp;
    cudaGetSymbolAddress((void**)&Xp,  g_X);
    cudaGetSymbolAddress((void**)&Qp,  g_Q);
    cudaGetSymbolAddress((void**)&Kp,  g_K);
    cudaGetSymbolAddress((void**)&Vp,  g_V);
    cudaGetSymbolAddress((void**)&Ap,  g_A);
    cudaGetSymbolAddress((void**)&WTp, g_WT);

    cudaFuncSetAttribute(attn_f16_kernel,
                         cudaFuncAttributeMaxDynamicSharedMemorySize,
                         ATTN_SMEM_BYTES);

    const size_t WSZ = (size_t)HID * HID;
    const float qscale = 0.08838834764831845f;   // 1/sqrt(128), plain (expf domain)

    prep_all<<<dim3(HID / 64, HID / 64, 5), 256>>>(Wq, Wk, Wv, Wo, WTp, x, Xp, qscale);

    gemm_f16<<<dim3(HID / TBN, MTOT / TBM, 3), 128>>>(Xp, WTp, Qp, Kp, Vp, 1);

    attn_f16_kernel<<<dim3(SEQ / 64, BATCH * NH), 128, ATTN_SMEM_BYTES>>>(Qp, Kp, Vp, Ap);

    gemm_f16<<<dim3(HID / TBN, MTOT / TBM, 1), 128>>>(Ap, WTp + 3 * WSZ,
                                                      d_out, nullptr, nullptr, 0);
}